// round 13
// baseline (speedup 1.0000x reference)
#include <cuda_runtime.h>

#define IMG   256
#define F_CNT 256
#define V_CNT 1024

// linspace(-1,1,256)[k]: XLA lowers start + iota*step, LLVM contracts to
// fma(k, step, -1). Endpoint exact.
__device__ __forceinline__ float lin_at(int k) {
    const float STEP = 2.0f / 255.0f;
    if (k == 255) return 1.0f;
    return __fmaf_rn((float)k, STEP, -1.0f);
}

// edge value at (qx,qy), anchored (ex,ey), deltas (dy,dx):
// E = fma(qx-ex, dy, -((qy-ey)*dx))   (bit-identical to reference contraction)
__device__ __forceinline__ float edge_at(float qx, float qy, float ex, float ey,
                                         float dy, float dx) {
    return __fmaf_rn(__fsub_rn(qx, ex), dy, -__fmul_rn(__fsub_rn(qy, ey), dx));
}

__global__ void __launch_bounds__(1024, 2) render_kernel(
    const float* __restrict__ vertices,
    const void*  __restrict__ faces,
    const float* __restrict__ uv,
    const void*  __restrict__ uvfaces,
    const float* __restrict__ uvmap,
    float*       __restrict__ out)
{
    // per-face packed data (compacted, tile-local):
    // [0] = (bx, by, ay-by, ax-bx)   edge AB
    // [1] = (cx, cy, by-cy, bx-cx)   edge CB
    // [2] = (ax, ay, cy-ay, cx-ax)   edge CA
    // [3] = (Asafe, zi0, zi1, zi2)
    // [4] = (u0, v0, u1, v1)
    // [5] = (u2, v2, -, -)
    __shared__ float4 sf[F_CNT][6];
    __shared__ unsigned long long skey[4][256];
    __shared__ float s_warpmin[32];
    __shared__ unsigned char s_anyf[32], s_anyu[32];
    __shared__ int warpcnt[8];

    const int tx = threadIdx.x, ty = threadIdx.y, tz = threadIdx.z;
    const int tid  = tx + ty * 16 + tz * 256;
    const int wid  = tid >> 5, lane = tid & 31;
    const int jt0 = blockIdx.x * 16, it0 = blockIdx.y * 16;

    // ---- phase 0: min-z partial reduce (1024 threads, 1 vertex each) ----
    float zm = vertices[tid * 3 + 2];
    #pragma unroll
    for (int o = 16; o; o >>= 1) zm = fminf(zm, __shfl_xor_sync(0xffffffffu, zm, o));
    if (lane == 0) s_warpmin[wid] = zm;

    // ---- dtype probe: high words of first 384 int64 entries are 0.
    // Reading 768 words is in-bounds for both int32 (768 w) and int64 (1536 w).
    unsigned pw = 0;
    if (wid < 12)       pw = ((const unsigned*)faces)[2 * tid + 1];
    else if (wid < 24)  pw = ((const unsigned*)uvfaces)[2 * (tid - 384) + 1];
    bool anyv = __any_sync(0xffffffffu, pw != 0u);
    if (lane == 0) {
        s_anyf[wid] = (wid < 12) && anyv;
        s_anyu[wid] = (wid >= 12 && wid < 24) && anyv;
    }
    __syncthreads();   // barrier #1

    // ---- uniform per-warp finish: zmin, dtype flags, t* (no serial section) ----
    int isf64, isu64;
    float tthr;
    {
        bool af = __any_sync(0xffffffffu, s_anyf[lane] != 0);
        bool au = __any_sync(0xffffffffu, s_anyu[lane] != 0);
        isf64 = !af; isu64 = !au;

        float z = s_warpmin[lane];
        #pragma unroll
        for (int o = 16; o; o >>= 1) z = fminf(z, __shfl_xor_sync(0xffffffffu, z, o));
        z = __shfl_sync(0xffffffffu, z, 0);

        // t* = max{ t : fdiv(1,t) >= zinit }  =>  (Z >= zinit) <=> (zinv <= t*).
        // Lane-parallel over the 9-ulp candidate window [t0-4, t0+4]
        // (same window the sequential ulp-walk searched => identical result).
        float t0 = __fdiv_rn(1.0f, z);
        int im = -1;
        if (lane < 9) {
            unsigned cb = __float_as_uint(t0) + (unsigned)(lane - 4);
            float c = __uint_as_float(cb);
            if (__fdiv_rn(1.0f, c) >= z) im = (int)cb;
        }
        im = __reduce_max_sync(0xffffffffu, im);
        tthr = __uint_as_float((unsigned)im);
    }

    // ---- phase 1: per-face precompute + tile cull (threads 0..255) ----
    float4 fd[6];
    bool flag = false;
    if (tid < 256) {
        const int f = tid;
        long long i0, i1, i2, j0, j1, j2;
        if (isf64) {
            const long long* p = (const long long*)faces;
            i0 = p[f*3]; i1 = p[f*3+1]; i2 = p[f*3+2];
        } else {
            const int* p = (const int*)faces;
            i0 = p[f*3]; i1 = p[f*3+1]; i2 = p[f*3+2];
        }
        if (isu64) {
            const long long* p = (const long long*)uvfaces;
            j0 = p[f*3]; j1 = p[f*3+1]; j2 = p[f*3+2];
        } else {
            const int* p = (const int*)uvfaces;
            j0 = p[f*3]; j1 = p[f*3+1]; j2 = p[f*3+2];
        }

        float ax = vertices[i0*3+0], ay = vertices[i0*3+1], az = vertices[i0*3+2];
        float bx = vertices[i1*3+0], by = vertices[i1*3+1], bz = vertices[i1*3+2];
        float cx = vertices[i2*3+0], cy = vertices[i2*3+1], cz = vertices[i2*3+2];

        // signed 2D area, LLVM-contracted: fma(d1, d2, -(d3*d4))
        float A = __fmaf_rn(__fsub_rn(bx, ax), __fsub_rn(cy, ay),
                            -__fmul_rn(__fsub_rn(by, ay), __fsub_rn(cx, ax)));
        float Asafe = (fabsf(A) < 1e-9f) ? 1.0f : A;

        float zi0 = __fdiv_rn(1.0f, az);
        float zi1 = __fdiv_rn(1.0f, bz);
        float zi2 = __fdiv_rn(1.0f, cz);

        // uvn = uv*2 - 1 contracts to fma(uv,2,-1); then * z_inv
        float u0 = __fmul_rn(__fmaf_rn(uv[j0*2+0], 2.0f, -1.0f), zi0);
        float v0 = __fmul_rn(__fmaf_rn(uv[j0*2+1], 2.0f, -1.0f), zi0);
        float u1 = __fmul_rn(__fmaf_rn(uv[j1*2+0], 2.0f, -1.0f), zi1);
        float v1 = __fmul_rn(__fmaf_rn(uv[j1*2+1], 2.0f, -1.0f), zi1);
        float u2 = __fmul_rn(__fmaf_rn(uv[j2*2+0], 2.0f, -1.0f), zi2);
        float v2 = __fmul_rn(__fmaf_rn(uv[j2*2+1], 2.0f, -1.0f), zi2);

        fd[0] = make_float4(bx, by, __fsub_rn(ay, by), __fsub_rn(ax, bx));
        fd[1] = make_float4(cx, cy, __fsub_rn(by, cy), __fsub_rn(bx, cx));
        fd[2] = make_float4(ax, ay, __fsub_rn(cy, ay), __fsub_rn(cx, ax));
        fd[3] = make_float4(Asafe, zi0, zi1, zi2);
        fd[4] = make_float4(u0, v0, u1, v1);
        fd[5] = make_float4(u2, v2, 0.f, 0.f);

        if (A >= 1e-9f) {
            // bbox pre-filter (±1 px margin)
            float minx = fminf(ax, fminf(bx, cx)), maxx = fmaxf(ax, fmaxf(bx, cx));
            float miny = fminf(ay, fminf(by, cy)), maxy = fmaxf(ay, fmaxf(by, cy));
            int jlo = max(0,   (int)floorf((minx + 1.0f) * 127.5f) - 1);
            int jhi = min(255, (int)ceilf ((maxx + 1.0f) * 127.5f) + 1);
            int klo = max(0,   (int)floorf((miny + 1.0f) * 127.5f) - 1);
            int khi = min(255, (int)ceilf ((maxy + 1.0f) * 127.5f) + 1);
            int ilo = 255 - khi, ihi = 255 - klo;
            flag = (jlo <= jt0 + 15) && (jhi >= jt0) && (ilo <= it0 + 15) && (ihi >= it0);

            if (flag) {
                // conservative tile-corner edge cull: an affine edge < -margin at
                // all 4 corners is < 0 across the tile (fp error << margin).
                const float MARGIN = -1e-3f;
                float qx0 = lin_at(jt0), qx1 = lin_at(jt0 + 15);
                float qy0 = lin_at(255 - (it0 + 15)), qy1 = lin_at(255 - it0);
                #pragma unroll
                for (int e = 0; e < 3; e++) {
                    float ex = fd[e].x, ey = fd[e].y, dy = fd[e].z, dx = fd[e].w;
                    float m = fmaxf(fmaxf(edge_at(qx0, qy0, ex, ey, dy, dx),
                                          edge_at(qx1, qy0, ex, ey, dy, dx)),
                                    fmaxf(edge_at(qx0, qy1, ex, ey, dy, dx),
                                          edge_at(qx1, qy1, ex, ey, dy, dx)));
                    if (m < MARGIN) flag = false;
                }
            }
        }
    }

    // ---- stable (index-order) compaction into sf ----
    unsigned bmask = 0;
    if (wid < 8) {
        bmask = __ballot_sync(0xffffffffu, flag);
        if (lane == 0) warpcnt[wid] = __popc(bmask);
    }
    __syncthreads();   // barrier #2

    // per-thread offset/count scan (uniform; no serial pass, no extra barrier)
    int nf = 0, off = 0;
    #pragma unroll
    for (int w = 0; w < 8; w++) {
        int c = warpcnt[w];
        if (w < wid) off += c;
        nf += c;
    }
    if (flag) {
        int pos = off + __popc(bmask & ((1u << lane) - 1u));
        #pragma unroll
        for (int q = 0; q < 6; q++) sf[pos][q] = fd[q];
    }
    __syncthreads();   // barrier #3

    // ---- main loop: thread tz scans faces k = tz, tz+4, ... ----
    const int j = jt0 + tx, i = it0 + ty;
    const float px = lin_at(j);
    const float py = lin_at(255 - i);   // rot90: py = lin[255-i]

    // winner = min (zinv_bits, face_idx) lexicographic  (argmax Z, first-index ties)
    unsigned long long bestkey = ~0ull;
    for (int k = tz; k < nf; k += 4) {
        float4 e0 = sf[k][0];
        float4 e1 = sf[k][1];
        float4 e2 = sf[k][2];
        float pAB = edge_at(px, py, e0.x, e0.y, e0.z, e0.w);
        float pCB = edge_at(px, py, e1.x, e1.y, e1.z, e1.w);
        float pCA = edge_at(px, py, e2.x, e2.y, e2.z, e2.w);

        if (pAB > 0.0f && pCB > 0.0f && pCA > 0.0f) {
            float4 zz = sf[k][3];   // Asafe, zi0, zi1, zi2
            float w1 = __fdiv_rn(pCB, zz.x);
            float w2 = __fdiv_rn(pCA, zz.x);
            float w3 = __fsub_rn(__fsub_rn(1.0f, w1), w2);
            float zinv = __fmaf_rn(w3, zz.w,
                         __fmaf_rn(w1, zz.y,
                         __fmul_rn(w2, zz.z)));
            // cover => zinv > 0; (Z >= zinit) <=> (zinv <= t*)
            if (zinv <= tthr) {
                unsigned long long key =
                    ((unsigned long long)__float_as_uint(zinv) << 32) | (unsigned)k;
                if (key < bestkey) bestkey = key;
            }
        }
    }
    skey[tz][ty * 16 + tx] = bestkey;
    __syncthreads();   // barrier #4

    // ---- epilogue (R5 shape: tz==0 only; avoids redundant fdiv work) ----
    if (tz == 0) {
        int pix = ty * 16 + tx;
        unsigned long long key = skey[0][pix];
        unsigned long long k1 = skey[1][pix]; if (k1 < key) key = k1;
        unsigned long long k2 = skey[2][pix]; if (k2 < key) key = k2;
        unsigned long long k3 = skey[3][pix]; if (k3 < key) key = k3;

        float r = 0.f, g = 0.f, b = 0.f, h = 0.f;
        if (key != ~0ull) {
            h = 1.0f;
            int bk = (int)(key & 0xFFFFFFFFull);
            float zinv = __uint_as_float((unsigned)(key >> 32));
            float Zw = __fdiv_rn(1.0f, zinv);   // == reference Zw bitwise

            float4 e1v = sf[bk][1];
            float4 e2v = sf[bk][2];
            float4 zz  = sf[bk][3];
            float pCB = edge_at(px, py, e1v.x, e1v.y, e1v.z, e1v.w);
            float pCA = edge_at(px, py, e2v.x, e2v.y, e2v.z, e2v.w);
            float w1 = __fdiv_rn(pCB, zz.x);
            float w2 = __fdiv_rn(pCA, zz.x);
            float w3 = __fsub_rn(__fsub_rn(1.0f, w1), w2);

            float4 uva = sf[bk][4];
            float4 uvb = sf[bk][5];
            float u = __fmaf_rn(w3, uvb.x,
                      __fmaf_rn(w1, uva.x,
                      __fmul_rn(w2, uva.z)));
            float v = __fmaf_rn(w3, uvb.y,
                      __fmaf_rn(w1, uva.y,
                      __fmul_rn(w2, uva.w)));
            float gx = __fmul_rn(u, Zw);
            float gy = __fmul_rn(v, Zw);

            // x = ((gx+1)*256 - 1)*0.5, contracted to fma(gx+1, 256, -1)
            float x = __fmul_rn(__fmaf_rn(__fadd_rn(gx, 1.0f), 256.0f, -1.0f), 0.5f);
            float y = __fmul_rn(__fmaf_rn(__fadd_rn(gy, 1.0f), 256.0f, -1.0f), 0.5f);
            float x0 = floorf(x), y0 = floorf(y);
            float x1 = __fadd_rn(x0, 1.0f), y1 = __fadd_rn(y0, 1.0f);
            float wx1 = __fsub_rn(x, x0), wx0 = __fsub_rn(1.0f, wx1);
            float wy1 = __fsub_rn(y, y0), wy0 = __fsub_rn(1.0f, wy1);

            bool v00 = (x0 >= 0.f) && (x0 <= 255.f) && (y0 >= 0.f) && (y0 <= 255.f);
            bool v10 = (x1 >= 0.f) && (x1 <= 255.f) && (y0 >= 0.f) && (y0 <= 255.f);
            bool v01 = (x0 >= 0.f) && (x0 <= 255.f) && (y1 >= 0.f) && (y1 <= 255.f);
            bool v11 = (x1 >= 0.f) && (x1 <= 255.f) && (y1 >= 0.f) && (y1 <= 255.f);

            int ix0 = (int)fminf(fmaxf(x0, 0.f), 255.f);
            int ix1 = (int)fminf(fmaxf(x1, 0.f), 255.f);
            int iy0 = (int)fminf(fmaxf(y0, 0.f), 255.f);
            int iy1 = (int)fminf(fmaxf(y1, 0.f), 255.f);

            float w00 = __fmul_rn(wx0, wy0);
            float w10 = __fmul_rn(wx1, wy0);
            float w01 = __fmul_rn(wx0, wy1);
            float w11 = __fmul_rn(wx1, wy1);

            int o00 = iy0 * 256 + ix0, o10 = iy0 * 256 + ix1;
            int o01 = iy1 * 256 + ix0, o11 = iy1 * 256 + ix1;

            float acc[3];
            #pragma unroll
            for (int c = 0; c < 3; c++) {
                const float* img = uvmap + c * 65536;
                float t00 = v00 ? __ldg(img + o00) : 0.f;
                float t10 = v10 ? __ldg(img + o10) : 0.f;
                float t01 = v01 ? __ldg(img + o01) : 0.f;
                float t11 = v11 ? __ldg(img + o11) : 0.f;
                acc[c] = __fmaf_rn(t11, w11,
                         __fmaf_rn(t01, w01,
                         __fmaf_rn(t00, w00,
                         __fmul_rn(t10, w10))));
            }
            r = acc[0]; g = acc[1]; b = acc[2];
        }

        int pidx = i * 256 + j;
        out[0 * 65536 + pidx] = r;
        out[1 * 65536 + pidx] = g;
        out[2 * 65536 + pidx] = b;
        out[3 * 65536 + pidx] = h;
    }
}

extern "C" void kernel_launch(void* const* d_in, const int* in_sizes, int n_in,
                              void* d_out, int out_size)
{
    const float* vertices = (const float*)d_in[0];
    const void*  faces    = d_in[1];
    const float* uv       = (const float*)d_in[2];
    const void*  uvfaces  = d_in[3];
    const float* uvmap    = (const float*)d_in[4];
    float* out = (float*)d_out;

    dim3 blk(16, 16, 4), grd(IMG / 16, IMG / 16);
    render_kernel<<<grd, blk>>>(vertices, faces, uv, uvfaces, uvmap, out);
}

// round 14
// speedup vs baseline: 1.0306x; 1.0306x over previous
#include <cuda_runtime.h>

#define IMG   256
#define F_CNT 256
#define V_CNT 1024

// linspace(-1,1,256)[k]: XLA lowers start + iota*step, LLVM contracts to
// fma(k, step, -1). Endpoint exact.
__device__ __forceinline__ float lin_at(int k) {
    const float STEP = 2.0f / 255.0f;
    if (k == 255) return 1.0f;
    return __fmaf_rn((float)k, STEP, -1.0f);
}

// edge value at (qx,qy), anchored (ex,ey), deltas (dy,dx):
// E = fma(qx-ex, dy, -((qy-ey)*dx))   (bit-identical to reference contraction)
__device__ __forceinline__ float edge_at(float qx, float qy, float ex, float ey,
                                         float dy, float dx) {
    return __fmaf_rn(__fsub_rn(qx, ex), dy, -__fmul_rn(__fsub_rn(qy, ey), dx));
}

__global__ void __launch_bounds__(1024, 2) render_kernel(
    const float* __restrict__ vertices,
    const void*  __restrict__ faces,
    const float* __restrict__ uv,
    const void*  __restrict__ uvfaces,
    const float* __restrict__ uvmap,
    float*       __restrict__ out)
{
    // per-face packed data (compacted, tile-local):
    // [0] = (bx, by, ay-by, ax-bx)   edge AB
    // [1] = (cx, cy, by-cy, bx-cx)   edge CB
    // [2] = (ax, ay, cy-ay, cx-ax)   edge CA
    // [3] = (Asafe, zi0, zi1, zi2)
    // [4] = (u0, v0, u1, v1)
    // [5] = (u2, v2, -, -)
    __shared__ float4 sf[F_CNT][6];
    __shared__ unsigned long long skey[4][256];
    __shared__ float2 swp[4][256];          // (w1,w2) of each slice's best face
    __shared__ float s_warpmin[32];
    __shared__ int warpcnt[8];

    const int tx = threadIdx.x, ty = threadIdx.y, tz = threadIdx.z;
    const int tid  = tx + ty * 16 + tz * 256;
    const int wid  = tid >> 5, lane = tid & 31;
    const int jt0 = blockIdx.x * 16, it0 = blockIdx.y * 16;

    // ================= phase 1: warps 0-7 — faces; warps 8-31 — min-z =======
    float4 fd[6];
    bool flag = false;
    if (tid < 256) {
        // -- warp-local dtype probe (no barrier): odd 32-bit words of the
        //    first 256 int64 entries are 0 iff int64. Word 2*tid+1 <= 511 is
        //    in-bounds for int32 too (768 words). P(false positive per warp)
        //    = 1024^-32 ~ 0 (random indices in [0,1024)).
        unsigned wf = ((const unsigned*)faces)[2 * tid + 1];
        unsigned wu = ((const unsigned*)uvfaces)[2 * tid + 1];
        bool isf64 = !__any_sync(0xffffffffu, wf != 0u);
        bool isu64 = !__any_sync(0xffffffffu, wu != 0u);

        const int f = tid;
        long long i0, i1, i2, j0, j1, j2;
        if (isf64) {
            const long long* p = (const long long*)faces;
            i0 = p[f*3]; i1 = p[f*3+1]; i2 = p[f*3+2];
        } else {
            const int* p = (const int*)faces;
            i0 = p[f*3]; i1 = p[f*3+1]; i2 = p[f*3+2];
        }
        if (isu64) {
            const long long* p = (const long long*)uvfaces;
            j0 = p[f*3]; j1 = p[f*3+1]; j2 = p[f*3+2];
        } else {
            const int* p = (const int*)uvfaces;
            j0 = p[f*3]; j1 = p[f*3+1]; j2 = p[f*3+2];
        }

        float ax = vertices[i0*3+0], ay = vertices[i0*3+1], az = vertices[i0*3+2];
        float bx = vertices[i1*3+0], by = vertices[i1*3+1], bz = vertices[i1*3+2];
        float cx = vertices[i2*3+0], cy = vertices[i2*3+1], cz = vertices[i2*3+2];

        // signed 2D area, LLVM-contracted: fma(d1, d2, -(d3*d4))
        float A = __fmaf_rn(__fsub_rn(bx, ax), __fsub_rn(cy, ay),
                            -__fmul_rn(__fsub_rn(by, ay), __fsub_rn(cx, ax)));
        float Asafe = (fabsf(A) < 1e-9f) ? 1.0f : A;

        float zi0 = __fdiv_rn(1.0f, az);
        float zi1 = __fdiv_rn(1.0f, bz);
        float zi2 = __fdiv_rn(1.0f, cz);

        // uvn = uv*2 - 1 contracts to fma(uv,2,-1); then * z_inv
        float u0 = __fmul_rn(__fmaf_rn(uv[j0*2+0], 2.0f, -1.0f), zi0);
        float v0 = __fmul_rn(__fmaf_rn(uv[j0*2+1], 2.0f, -1.0f), zi0);
        float u1 = __fmul_rn(__fmaf_rn(uv[j1*2+0], 2.0f, -1.0f), zi1);
        float v1 = __fmul_rn(__fmaf_rn(uv[j1*2+1], 2.0f, -1.0f), zi1);
        float u2 = __fmul_rn(__fmaf_rn(uv[j2*2+0], 2.0f, -1.0f), zi2);
        float v2 = __fmul_rn(__fmaf_rn(uv[j2*2+1], 2.0f, -1.0f), zi2);

        fd[0] = make_float4(bx, by, __fsub_rn(ay, by), __fsub_rn(ax, bx));
        fd[1] = make_float4(cx, cy, __fsub_rn(by, cy), __fsub_rn(bx, cx));
        fd[2] = make_float4(ax, ay, __fsub_rn(cy, ay), __fsub_rn(cx, ax));
        fd[3] = make_float4(Asafe, zi0, zi1, zi2);
        fd[4] = make_float4(u0, v0, u1, v1);
        fd[5] = make_float4(u2, v2, 0.f, 0.f);

        if (A >= 1e-9f) {
            // bbox pre-filter (±1 px margin)
            float minx = fminf(ax, fminf(bx, cx)), maxx = fmaxf(ax, fmaxf(bx, cx));
            float miny = fminf(ay, fminf(by, cy)), maxy = fmaxf(ay, fmaxf(by, cy));
            int jlo = max(0,   (int)floorf((minx + 1.0f) * 127.5f) - 1);
            int jhi = min(255, (int)ceilf ((maxx + 1.0f) * 127.5f) + 1);
            int klo = max(0,   (int)floorf((miny + 1.0f) * 127.5f) - 1);
            int khi = min(255, (int)ceilf ((maxy + 1.0f) * 127.5f) + 1);
            int ilo = 255 - khi, ihi = 255 - klo;
            flag = (jlo <= jt0 + 15) && (jhi >= jt0) && (ilo <= it0 + 15) && (ihi >= it0);

            if (flag) {
                // conservative tile-corner edge cull: an affine edge < -margin at
                // all 4 corners is < 0 across the tile (fp error << margin).
                const float MARGIN = -1e-3f;
                float qx0 = lin_at(jt0), qx1 = lin_at(jt0 + 15);
                float qy0 = lin_at(255 - (it0 + 15)), qy1 = lin_at(255 - it0);
                #pragma unroll
                for (int e = 0; e < 3; e++) {
                    float ex = fd[e].x, ey = fd[e].y, dy = fd[e].z, dx = fd[e].w;
                    float m = fmaxf(fmaxf(edge_at(qx0, qy0, ex, ey, dy, dx),
                                          edge_at(qx1, qy0, ex, ey, dy, dx)),
                                    fmaxf(edge_at(qx0, qy1, ex, ey, dy, dx),
                                          edge_at(qx1, qy1, ex, ey, dy, dx)));
                    if (m < MARGIN) flag = false;
                }
            }
        }
    } else {
        // -- min-z over all 1024 vertices (768 threads; first 256 take two) --
        int q = tid - 256;
        float zm = vertices[q * 3 + 2];
        if (q < 256) zm = fminf(zm, vertices[(q + 768) * 3 + 2]);
        #pragma unroll
        for (int o = 16; o; o >>= 1) zm = fminf(zm, __shfl_xor_sync(0xffffffffu, zm, o));
        if (lane == 0) s_warpmin[wid] = zm;
    }

    unsigned bmask = 0;
    if (wid < 8) {
        bmask = __ballot_sync(0xffffffffu, flag);
        if (lane == 0) warpcnt[wid] = __popc(bmask);
    }
    __syncthreads();   // barrier #1

    // ---- uniform: t* from zmin (all warps; off the phase-1 critical path) ----
    float tthr;
    {
        float z = (lane < 24) ? s_warpmin[8 + lane] : 3.0e38f;
        #pragma unroll
        for (int o = 16; o; o >>= 1) z = fminf(z, __shfl_xor_sync(0xffffffffu, z, o));
        z = __shfl_sync(0xffffffffu, z, 0);
        // t* = max{ t : fdiv(1,t) >= zinit }  =>  (Z >= zinit) <=> (zinv <= t*).
        // Lane-parallel over the 9-ulp window [t0-4, t0+4].
        float t0 = __fdiv_rn(1.0f, z);
        int im = -1;
        if (lane < 9) {
            unsigned cb = __float_as_uint(t0) + (unsigned)(lane - 4);
            float c = __uint_as_float(cb);
            if (__fdiv_rn(1.0f, c) >= z) im = (int)cb;
        }
        im = __reduce_max_sync(0xffffffffu, im);
        tthr = __uint_as_float((unsigned)im);
    }

    // per-thread offset/count scan (uniform) + stable compaction
    int nf = 0, off = 0;
    #pragma unroll
    for (int w = 0; w < 8; w++) {
        int c = warpcnt[w];
        if (w < wid) off += c;
        nf += c;
    }
    if (flag) {
        int pos = off + __popc(bmask & ((1u << lane) - 1u));
        #pragma unroll
        for (int q = 0; q < 6; q++) sf[pos][q] = fd[q];
    }
    __syncthreads();   // barrier #2

    // ---- main loop: thread tz scans faces k = tz, tz+4, ... ----
    const int j = jt0 + tx, i = it0 + ty;
    const int pix = ty * 16 + tx;
    const float px = lin_at(j);
    const float py = lin_at(255 - i);   // rot90: py = lin[255-i]

    // winner = min (zinv_bits, face_idx) lexicographic  (argmax Z, first-index ties)
    unsigned long long bestkey = ~0ull;
    for (int k = tz; k < nf; k += 4) {
        float4 e0 = sf[k][0];
        float4 e1 = sf[k][1];
        float4 e2 = sf[k][2];
        float pAB = edge_at(px, py, e0.x, e0.y, e0.z, e0.w);
        float pCB = edge_at(px, py, e1.x, e1.y, e1.z, e1.w);
        float pCA = edge_at(px, py, e2.x, e2.y, e2.z, e2.w);

        if (pAB > 0.0f && pCB > 0.0f && pCA > 0.0f) {
            float4 zz = sf[k][3];   // Asafe, zi0, zi1, zi2
            float w1 = __fdiv_rn(pCB, zz.x);
            float w2 = __fdiv_rn(pCA, zz.x);
            float w3 = __fsub_rn(__fsub_rn(1.0f, w1), w2);
            float zinv = __fmaf_rn(w3, zz.w,
                         __fmaf_rn(w1, zz.y,
                         __fmul_rn(w2, zz.z)));
            // cover => zinv > 0; (Z >= zinit) <=> (zinv <= t*)
            if (zinv <= tthr) {
                unsigned long long key =
                    ((unsigned long long)__float_as_uint(zinv) << 32) | (unsigned)k;
                if (key < bestkey) {
                    bestkey = key;
                    swp[tz][pix] = make_float2(w1, w2);  // forward barycentrics
                }
            }
        }
    }
    skey[tz][pix] = bestkey;
    __syncthreads();   // barrier #3

    // ---- epilogue (tz==0 only; winner's (w1,w2) forwarded via swp) ----
    if (tz == 0) {
        unsigned long long k0 = skey[0][pix];
        unsigned long long k1 = skey[1][pix];
        unsigned long long k2 = skey[2][pix];
        unsigned long long k3 = skey[3][pix];
        unsigned long long key = k0;
        if (k1 < key) key = k1;
        if (k2 < key) key = k2;
        if (k3 < key) key = k3;

        float r = 0.f, g = 0.f, b = 0.f, h = 0.f;
        if (key != ~0ull) {
            h = 1.0f;
            int bk = (int)(key & 0xFFFFFFFFull);
            float zinv = __uint_as_float((unsigned)(key >> 32));
            float Zw = __fdiv_rn(1.0f, zinv);   // == reference Zw bitwise

            // winning slice (keys distinct across slices: k % 4 == tz)
            int sw = (key == k0) ? 0 : (key == k1) ? 1 : (key == k2) ? 2 : 3;
            float2 wv = swp[sw][pix];
            float w1 = wv.x, w2 = wv.y;
            float w3 = __fsub_rn(__fsub_rn(1.0f, w1), w2);

            float4 uva = sf[bk][4];
            float4 uvb = sf[bk][5];
            float u = __fmaf_rn(w3, uvb.x,
                      __fmaf_rn(w1, uva.x,
                      __fmul_rn(w2, uva.z)));
            float v = __fmaf_rn(w3, uvb.y,
                      __fmaf_rn(w1, uva.y,
                      __fmul_rn(w2, uva.w)));
            float gx = __fmul_rn(u, Zw);
            float gy = __fmul_rn(v, Zw);

            // x = ((gx+1)*256 - 1)*0.5, contracted to fma(gx+1, 256, -1)
            float x = __fmul_rn(__fmaf_rn(__fadd_rn(gx, 1.0f), 256.0f, -1.0f), 0.5f);
            float y = __fmul_rn(__fmaf_rn(__fadd_rn(gy, 1.0f), 256.0f, -1.0f), 0.5f);
            float x0 = floorf(x), y0 = floorf(y);
            float x1 = __fadd_rn(x0, 1.0f), y1 = __fadd_rn(y0, 1.0f);
            float wx1 = __fsub_rn(x, x0), wx0 = __fsub_rn(1.0f, wx1);
            float wy1 = __fsub_rn(y, y0), wy0 = __fsub_rn(1.0f, wy1);

            bool v00 = (x0 >= 0.f) && (x0 <= 255.f) && (y0 >= 0.f) && (y0 <= 255.f);
            bool v10 = (x1 >= 0.f) && (x1 <= 255.f) && (y0 >= 0.f) && (y0 <= 255.f);
            bool v01 = (x0 >= 0.f) && (x0 <= 255.f) && (y1 >= 0.f) && (y1 <= 255.f);
            bool v11 = (x1 >= 0.f) && (x1 <= 255.f) && (y1 >= 0.f) && (y1 <= 255.f);

            int ix0 = (int)fminf(fmaxf(x0, 0.f), 255.f);
            int ix1 = (int)fminf(fmaxf(x1, 0.f), 255.f);
            int iy0 = (int)fminf(fmaxf(y0, 0.f), 255.f);
            int iy1 = (int)fminf(fmaxf(y1, 0.f), 255.f);

            float w00 = __fmul_rn(wx0, wy0);
            float w10 = __fmul_rn(wx1, wy0);
            float w01 = __fmul_rn(wx0, wy1);
            float w11 = __fmul_rn(wx1, wy1);

            int o00 = iy0 * 256 + ix0, o10 = iy0 * 256 + ix1;
            int o01 = iy1 * 256 + ix0, o11 = iy1 * 256 + ix1;

            float acc[3];
            #pragma unroll
            for (int c = 0; c < 3; c++) {
                const float* img = uvmap + c * 65536;
                float t00 = v00 ? __ldg(img + o00) : 0.f;
                float t10 = v10 ? __ldg(img + o10) : 0.f;
                float t01 = v01 ? __ldg(img + o01) : 0.f;
                float t11 = v11 ? __ldg(img + o11) : 0.f;
                acc[c] = __fmaf_rn(t11, w11,
                         __fmaf_rn(t01, w01,
                         __fmaf_rn(t00, w00,
                         __fmul_rn(t10, w10))));
            }
            r = acc[0]; g = acc[1]; b = acc[2];
        }

        int pidx = i * 256 + j;
        out[0 * 65536 + pidx] = r;
        out[1 * 65536 + pidx] = g;
        out[2 * 65536 + pidx] = b;
        out[3 * 65536 + pidx] = h;
    }
}

extern "C" void kernel_launch(void* const* d_in, const int* in_sizes, int n_in,
                              void* d_out, int out_size)
{
    const float* vertices = (const float*)d_in[0];
    const void*  faces    = d_in[1];
    const float* uv       = (const float*)d_in[2];
    const void*  uvfaces  = d_in[3];
    const float* uvmap    = (const float*)d_in[4];
    float* out = (float*)d_out;

    dim3 blk(16, 16, 4), grd(IMG / 16, IMG / 16);
    render_kernel<<<grd, blk>>>(vertices, faces, uv, uvfaces, uvmap, out);
}

// round 17
// speedup vs baseline: 1.1830x; 1.1479x over previous
#include <cuda_runtime.h>

#define IMG   256
#define F_CNT 256
#define V_CNT 1024

// linspace(-1,1,256)[k]: XLA lowers start + iota*step, LLVM contracts to
// fma(k, step, -1). Endpoint exact.
__device__ __forceinline__ float lin_at(int k) {
    const float STEP = 2.0f / 255.0f;
    if (k == 255) return 1.0f;
    return __fmaf_rn((float)k, STEP, -1.0f);
}

// edge value at (qx,qy), anchored (ex,ey), deltas (dy,dx):
// E = fma(qx-ex, dy, -((qy-ey)*dx))   (bit-identical to reference contraction)
__device__ __forceinline__ float edge_at(float qx, float qy, float ex, float ey,
                                         float dy, float dx) {
    return __fmaf_rn(__fsub_rn(qx, ex), dy, -__fmul_rn(__fsub_rn(qy, ey), dx));
}

__global__ void __launch_bounds__(1024, 2) render_kernel(
    const float* __restrict__ vertices,
    const void*  __restrict__ faces,
    const float* __restrict__ uv,
    const void*  __restrict__ uvfaces,
    const float* __restrict__ uvmap,
    float*       __restrict__ out)
{
    // per-face packed data (compacted, tile-local):
    // [0] = (bx, by, ay-by, ax-bx)   edge AB
    // [1] = (cx, cy, by-cy, bx-cx)   edge CB
    // [2] = (ax, ay, cy-ay, cx-ax)   edge CA
    // [3] = (Asafe, zi0, zi1, zi2)
    // [4] = (u0, v0, u1, v1)
    // [5] = (u2, v2, -, -)
    __shared__ float4 sf[F_CNT + 4][6];     // +4: room for sentinel padding
    __shared__ unsigned long long skey[4][256];
    __shared__ float2 swp[4][256];          // (w1,w2) of each slice's best face
    __shared__ float s_warpmin[32];
    __shared__ int warpcnt[8];

    const int tx = threadIdx.x, ty = threadIdx.y, tz = threadIdx.z;
    const int tid  = tx + ty * 16 + tz * 256;
    const int wid  = tid >> 5, lane = tid & 31;
    const int jt0 = blockIdx.x * 16, it0 = blockIdx.y * 16;

    // ================= phase 1: warps 0-7 — faces; warps 8-31 — min-z =======
    float4 fd[6];
    bool flag = false;
    if (tid < 256) {
        // -- warp-local dtype probe (no barrier): odd 32-bit words of the
        //    first 256 int64 entries are 0 iff int64. Word 2*tid+1 <= 511 is
        //    in-bounds for int32 too (768 words). P(false positive per warp)
        //    = 1024^-32 ~ 0 (random indices in [0,1024)).
        unsigned wf = ((const unsigned*)faces)[2 * tid + 1];
        unsigned wu = ((const unsigned*)uvfaces)[2 * tid + 1];
        bool isf64 = !__any_sync(0xffffffffu, wf != 0u);
        bool isu64 = !__any_sync(0xffffffffu, wu != 0u);

        const int f = tid;
        long long i0, i1, i2, j0, j1, j2;
        if (isf64) {
            const long long* p = (const long long*)faces;
            i0 = p[f*3]; i1 = p[f*3+1]; i2 = p[f*3+2];
        } else {
            const int* p = (const int*)faces;
            i0 = p[f*3]; i1 = p[f*3+1]; i2 = p[f*3+2];
        }
        if (isu64) {
            const long long* p = (const long long*)uvfaces;
            j0 = p[f*3]; j1 = p[f*3+1]; j2 = p[f*3+2];
        } else {
            const int* p = (const int*)uvfaces;
            j0 = p[f*3]; j1 = p[f*3+1]; j2 = p[f*3+2];
        }

        float ax = vertices[i0*3+0], ay = vertices[i0*3+1], az = vertices[i0*3+2];
        float bx = vertices[i1*3+0], by = vertices[i1*3+1], bz = vertices[i1*3+2];
        float cx = vertices[i2*3+0], cy = vertices[i2*3+1], cz = vertices[i2*3+2];

        // signed 2D area, LLVM-contracted: fma(d1, d2, -(d3*d4))
        float A = __fmaf_rn(__fsub_rn(bx, ax), __fsub_rn(cy, ay),
                            -__fmul_rn(__fsub_rn(by, ay), __fsub_rn(cx, ax)));
        float Asafe = (fabsf(A) < 1e-9f) ? 1.0f : A;

        float zi0 = __fdiv_rn(1.0f, az);
        float zi1 = __fdiv_rn(1.0f, bz);
        float zi2 = __fdiv_rn(1.0f, cz);

        // uvn = uv*2 - 1 contracts to fma(uv,2,-1); then * z_inv
        float u0 = __fmul_rn(__fmaf_rn(uv[j0*2+0], 2.0f, -1.0f), zi0);
        float v0 = __fmul_rn(__fmaf_rn(uv[j0*2+1], 2.0f, -1.0f), zi0);
        float u1 = __fmul_rn(__fmaf_rn(uv[j1*2+0], 2.0f, -1.0f), zi1);
        float v1 = __fmul_rn(__fmaf_rn(uv[j1*2+1], 2.0f, -1.0f), zi1);
        float u2 = __fmul_rn(__fmaf_rn(uv[j2*2+0], 2.0f, -1.0f), zi2);
        float v2 = __fmul_rn(__fmaf_rn(uv[j2*2+1], 2.0f, -1.0f), zi2);

        fd[0] = make_float4(bx, by, __fsub_rn(ay, by), __fsub_rn(ax, bx));
        fd[1] = make_float4(cx, cy, __fsub_rn(by, cy), __fsub_rn(bx, cx));
        fd[2] = make_float4(ax, ay, __fsub_rn(cy, ay), __fsub_rn(cx, ax));
        fd[3] = make_float4(Asafe, zi0, zi1, zi2);
        fd[4] = make_float4(u0, v0, u1, v1);
        fd[5] = make_float4(u2, v2, 0.f, 0.f);

        if (A >= 1e-9f) {
            // bbox pre-filter (±1 px margin)
            float minx = fminf(ax, fminf(bx, cx)), maxx = fmaxf(ax, fmaxf(bx, cx));
            float miny = fminf(ay, fminf(by, cy)), maxy = fmaxf(ay, fmaxf(by, cy));
            int jlo = max(0,   (int)floorf((minx + 1.0f) * 127.5f) - 1);
            int jhi = min(255, (int)ceilf ((maxx + 1.0f) * 127.5f) + 1);
            int klo = max(0,   (int)floorf((miny + 1.0f) * 127.5f) - 1);
            int khi = min(255, (int)ceilf ((maxy + 1.0f) * 127.5f) + 1);
            int ilo = 255 - khi, ihi = 255 - klo;
            flag = (jlo <= jt0 + 15) && (jhi >= jt0) && (ilo <= it0 + 15) && (ihi >= it0);

            if (flag) {
                // conservative tile-corner edge cull: an affine edge < -margin at
                // all 4 corners is < 0 across the tile (fp error << margin).
                const float MARGIN = -1e-3f;
                float qx0 = lin_at(jt0), qx1 = lin_at(jt0 + 15);
                float qy0 = lin_at(255 - (it0 + 15)), qy1 = lin_at(255 - it0);
                #pragma unroll
                for (int e = 0; e < 3; e++) {
                    float ex = fd[e].x, ey = fd[e].y, dy = fd[e].z, dx = fd[e].w;
                    float m = fmaxf(fmaxf(edge_at(qx0, qy0, ex, ey, dy, dx),
                                          edge_at(qx1, qy0, ex, ey, dy, dx)),
                                    fmaxf(edge_at(qx0, qy1, ex, ey, dy, dx),
                                          edge_at(qx1, qy1, ex, ey, dy, dx)));
                    if (m < MARGIN) flag = false;
                }
            }
        }
    } else {
        // -- min-z over all 1024 vertices (768 threads; first 256 take two) --
        int q = tid - 256;
        float zm = vertices[q * 3 + 2];
        if (q < 256) zm = fminf(zm, vertices[(q + 768) * 3 + 2]);
        #pragma unroll
        for (int o = 16; o; o >>= 1) zm = fminf(zm, __shfl_xor_sync(0xffffffffu, zm, o));
        if (lane == 0) s_warpmin[wid] = zm;
    }

    unsigned bmask = 0;
    if (wid < 8) {
        bmask = __ballot_sync(0xffffffffu, flag);
        if (lane == 0) warpcnt[wid] = __popc(bmask);
    }
    __syncthreads();   // barrier #1

    // ---- uniform: t* from zmin (all warps; off the phase-1 critical path) ----
    float tthr;
    {
        float z = (lane < 24) ? s_warpmin[8 + lane] : 3.0e38f;
        #pragma unroll
        for (int o = 16; o; o >>= 1) z = fminf(z, __shfl_xor_sync(0xffffffffu, z, o));
        z = __shfl_sync(0xffffffffu, z, 0);
        // t* = max{ t : fdiv(1,t) >= zinit }  =>  (Z >= zinit) <=> (zinv <= t*).
        // Lane-parallel over the 9-ulp window [t0-4, t0+4].
        float t0 = __fdiv_rn(1.0f, z);
        int im = -1;
        if (lane < 9) {
            unsigned cb = __float_as_uint(t0) + (unsigned)(lane - 4);
            float c = __uint_as_float(cb);
            if (__fdiv_rn(1.0f, c) >= z) im = (int)cb;
        }
        im = __reduce_max_sync(0xffffffffu, im);
        tthr = __uint_as_float((unsigned)im);
    }

    // per-thread offset/count scan (uniform) + stable compaction
    int nf = 0, off = 0;
    #pragma unroll
    for (int w = 0; w < 8; w++) {
        int c = warpcnt[w];
        if (w < wid) off += c;
        nf += c;
    }
    if (flag) {
        int pos = off + __popc(bmask & ((1u << lane) - 1u));
        #pragma unroll
        for (int q = 0; q < 6; q++) sf[pos][q] = fd[q];
    }
    // sentinel padding to multiple of 4: zero edges -> cover always fails,
    // attrs never read. Uniform trip counts across all tz slices.
    int pad = (4 - (nf & 3)) & 3;
    if (tid < pad) {
        float4 zf = make_float4(0.f, 0.f, 0.f, 0.f);
        sf[nf + tid][0] = zf;
        sf[nf + tid][1] = zf;
        sf[nf + tid][2] = zf;
    }
    const int nf4 = nf + pad;
    __syncthreads();   // barrier #2

    // ---- main loop: thread tz scans faces k = tz, tz+4, ... (uniform trips) --
    const int j = jt0 + tx, i = it0 + ty;
    const int pix = ty * 16 + tx;
    const float px = lin_at(j);
    const float py = lin_at(255 - i);   // rot90: py = lin[255-i]

    // Fused threshold: for positive floats, (zinv <= tthr) <=> key < KINIT
    // where KINIT = (tthr_bits+1) << 32. Any zinv > tthr keys >= KINIT.
    // winner = lexicographic min of (zinv_bits, face_idx) (argmax Z, first-tie).
    const unsigned long long KINIT =
        ((unsigned long long)(__float_as_uint(tthr) + 1u)) << 32;
    unsigned long long bestkey = KINIT;
    for (int k = tz; k < nf4; k += 4) {
        float4 e0 = sf[k][0];
        float4 e1 = sf[k][1];
        float4 e2 = sf[k][2];
        float pAB = edge_at(px, py, e0.x, e0.y, e0.z, e0.w);
        float pCB = edge_at(px, py, e1.x, e1.y, e1.z, e1.w);
        float pCA = edge_at(px, py, e2.x, e2.y, e2.z, e2.w);

        // all three > 0  <=>  min > 0 (edges finite, never NaN)
        if (fminf(pAB, fminf(pCB, pCA)) > 0.0f) {
            float4 zz = sf[k][3];   // Asafe, zi0, zi1, zi2
            float w1 = __fdiv_rn(pCB, zz.x);
            float w2 = __fdiv_rn(pCA, zz.x);
            float w3 = __fsub_rn(__fsub_rn(1.0f, w1), w2);
            float zinv = __fmaf_rn(w3, zz.w,
                         __fmaf_rn(w1, zz.y,
                         __fmul_rn(w2, zz.z)));
            unsigned long long key =
                ((unsigned long long)__float_as_uint(zinv) << 32) | (unsigned)k;
            if (key < bestkey) {
                bestkey = key;
                swp[tz][pix] = make_float2(w1, w2);  // forward barycentrics
            }
        }
    }
    skey[tz][pix] = bestkey;
    __syncthreads();   // barrier #3

    // ---- epilogue (tz==0 only; winner's (w1,w2) forwarded via swp) ----
    if (tz == 0) {
        unsigned long long k0 = skey[0][pix];
        unsigned long long k1 = skey[1][pix];
        unsigned long long k2 = skey[2][pix];
        unsigned long long k3 = skey[3][pix];
        unsigned long long key = k0;
        if (k1 < key) key = k1;
        if (k2 < key) key = k2;
        if (k3 < key) key = k3;

        float r = 0.f, g = 0.f, b = 0.f, h = 0.f;
        if (key != KINIT) {          // hit <=> some candidate beat the threshold
            h = 1.0f;
            int bk = (int)(key & 0xFFFFFFFFull);
            float zinv = __uint_as_float((unsigned)(key >> 32));
            float Zw = __fdiv_rn(1.0f, zinv);   // == reference Zw bitwise

            // winning slice (keys distinct across slices: k % 4 == tz)
            int sw = (key == k0) ? 0 : (key == k1) ? 1 : (key == k2) ? 2 : 3;
            float2 wv = swp[sw][pix];
            float w1 = wv.x, w2 = wv.y;
            float w3 = __fsub_rn(__fsub_rn(1.0f, w1), w2);

            float4 uva = sf[bk][4];
            float4 uvb = sf[bk][5];
            float u = __fmaf_rn(w3, uvb.x,
                      __fmaf_rn(w1, uva.x,
                      __fmul_rn(w2, uva.z)));
            float v = __fmaf_rn(w3, uvb.y,
                      __fmaf_rn(w1, uva.y,
                      __fmul_rn(w2, uva.w)));
            float gx = __fmul_rn(u, Zw);
            float gy = __fmul_rn(v, Zw);

            // x = ((gx+1)*256 - 1)*0.5, contracted to fma(gx+1, 256, -1)
            float x = __fmul_rn(__fmaf_rn(__fadd_rn(gx, 1.0f), 256.0f, -1.0f), 0.5f);
            float y = __fmul_rn(__fmaf_rn(__fadd_rn(gy, 1.0f), 256.0f, -1.0f), 0.5f);
            float x0 = floorf(x), y0 = floorf(y);
            float x1 = __fadd_rn(x0, 1.0f), y1 = __fadd_rn(y0, 1.0f);
            float wx1 = __fsub_rn(x, x0), wx0 = __fsub_rn(1.0f, wx1);
            float wy1 = __fsub_rn(y, y0), wy0 = __fsub_rn(1.0f, wy1);

            bool v00 = (x0 >= 0.f) && (x0 <= 255.f) && (y0 >= 0.f) && (y0 <= 255.f);
            bool v10 = (x1 >= 0.f) && (x1 <= 255.f) && (y0 >= 0.f) && (y0 <= 255.f);
            bool v01 = (x0 >= 0.f) && (x0 <= 255.f) && (y1 >= 0.f) && (y1 <= 255.f);
            bool v11 = (x1 >= 0.f) && (x1 <= 255.f) && (y1 >= 0.f) && (y1 <= 255.f);

            int ix0 = (int)fminf(fmaxf(x0, 0.f), 255.f);
            int ix1 = (int)fminf(fmaxf(x1, 0.f), 255.f);
            int iy0 = (int)fminf(fmaxf(y0, 0.f), 255.f);
            int iy1 = (int)fminf(fmaxf(y1, 0.f), 255.f);

            float w00 = __fmul_rn(wx0, wy0);
            float w10 = __fmul_rn(wx1, wy0);
            float w01 = __fmul_rn(wx0, wy1);
            float w11 = __fmul_rn(wx1, wy1);

            int o00 = iy0 * 256 + ix0, o10 = iy0 * 256 + ix1;
            int o01 = iy1 * 256 + ix0, o11 = iy1 * 256 + ix1;

            float acc[3];
            #pragma unroll
            for (int c = 0; c < 3; c++) {
                const float* img = uvmap + c * 65536;
                float t00 = v00 ? __ldg(img + o00) : 0.f;
                float t10 = v10 ? __ldg(img + o10) : 0.f;
                float t01 = v01 ? __ldg(img + o01) : 0.f;
                float t11 = v11 ? __ldg(img + o11) : 0.f;
                acc[c] = __fmaf_rn(t11, w11,
                         __fmaf_rn(t01, w01,
                         __fmaf_rn(t00, w00,
                         __fmul_rn(t10, w10))));
            }
            r = acc[0]; g = acc[1]; b = acc[2];
        }

        int pidx = i * 256 + j;
        out[0 * 65536 + pidx] = r;
        out[1 * 65536 + pidx] = g;
        out[2 * 65536 + pidx] = b;
        out[3 * 65536 + pidx] = h;
    }
}

extern "C" void kernel_launch(void* const* d_in, const int* in_sizes, int n_in,
                              void* d_out, int out_size)
{
    const float* vertices = (const float*)d_in[0];
    const void*  faces    = d_in[1];
    const float* uv       = (const float*)d_in[2];
    const void*  uvfaces  = d_in[3];
    const float* uvmap    = (const float*)d_in[4];
    float* out = (float*)d_out;

    dim3 blk(16, 16, 4), grd(IMG / 16, IMG / 16);
    render_kernel<<<grd, blk>>>(vertices, faces, uv, uvfaces, uvmap, out);
}